// round 15
// baseline (speedup 1.0000x reference)
#include <cuda_runtime.h>
#include <cuda_fp16.h>
#include <cstdint>

// ============================================================================
// LSTMCell: gates = [x|h] @ [Wx|Wh]^T + b, then elementwise LSTM math.
// M=16384, N=2048 (4 gates x 512), K=1024.  fp16 tcgen05 GEMM, fp32 accum.
//
// Live path: tcgen05 (sm_103a gencode), PERSISTENT CTAs:
//   grid = 128 CTAs, each runs 4 consecutive (nblk, m-pair) tiles.
//   Producer warp (16) + MMA warp (17) stream all 4 tiles back-to-back
//   through a 4-stage / 32KB pipeline (never drains); 16 epilogue warps
//   process tile t's TMEM D while tile t+1's operands are delivered.
//   done-mbar gates readout; epi-mbar gates D reuse (en=0 overwrite).
//   CTA tile = 2 m-tiles x 256 N (W-chunk reuse x2 -> 524 MB operands).
// (R14 was a broker/container infra failure; this is the unchanged resubmit.)
// ============================================================================

#define DINL __device__ __forceinline__

#if defined(__CUDA_ARCH__)
# if defined(__CUDA_ARCH_FEAT_SM103_ALL) || defined(__CUDA_ARCH_FEAT_SM100_ALL)
#  define TC_OK 1
# else
#  define TC_OK 0
# endif
#else
# define TC_OK 0
#endif

constexpr int B_SZ   = 16384;
constexpr int HIDN   = 512;
constexpr int KDIM   = 1024;
constexpr int TILE_M = 128;
constexpr int MMA_N  = 256;               // 4 gates * 64 hidden cols
constexpr int K_CHUNK = 32;               // fp16 elems per chunk (64 bytes/row)
constexpr int N_CHUNKS = KDIM / K_CHUNK;  // 32
constexpr int A_BYTES = TILE_M * 64;      // 8192 per m-tile chunk
constexpr int B_BYTES = MMA_N * 64;       // 16384
constexpr int STAGE_BYTES = 2 * A_BYTES + B_BYTES; // 32768
constexpr int TCS = 4;                    // 4 stages = 128KB
constexpr int ITEMS = 4;                  // tiles per persistent CTA
constexpr int GRID_X = 128;               // 128 * 4 = 512 work items

constexpr int SMEM_HDR = 2048;
constexpr int SMEM_TOTAL_TC = SMEM_HDR + TCS * STAGE_BYTES;   // 133120
constexpr int TC_THREADS = 576;           // 16 epi warps + producer + mma

// Pre-packed operands (device globals; no runtime allocation).
__device__ __align__(1024) __half g_A[B_SZ / TILE_M][N_CHUNKS][TILE_M * K_CHUNK];
__device__ __align__(1024) __half g_W[8][N_CHUNKS][MMA_N * K_CHUNK];
__device__ float g_bias[4 * HIDN];

DINL uint32_t smem_u32(const void* p) {
    uint32_t a;
    asm("{ .reg .u64 t; cvta.to.shared.u64 t, %1; cvt.u32.u64 %0, t; }" : "=r"(a) : "l"(p));
    return a;
}
DINL void mbar_init(uint32_t a, uint32_t cnt) {
    asm volatile("mbarrier.init.shared.b64 [%0], %1;" :: "r"(a), "r"(cnt) : "memory");
}
DINL void mbar_expect_tx(uint32_t a, uint32_t bytes) {
    asm volatile("mbarrier.arrive.expect_tx.shared.b64 _, [%0], %1;" :: "r"(a), "r"(bytes) : "memory");
}
DINL void mbar_arrive(uint32_t a) {
    asm volatile("mbarrier.arrive.shared.b64 _, [%0];" :: "r"(a) : "memory");
}
DINL void mbar_wait(uint32_t a, uint32_t parity) {
    asm volatile(
        "{\n\t.reg .pred P;\n\t"
        "W_%=:\n\t"
        "mbarrier.try_wait.parity.acquire.cta.shared::cta.b64 P, [%0], %1, 0x989680;\n\t"
        "@P bra.uni D_%=;\n\t"
        "bra.uni W_%=;\n\t"
        "D_%=:\n\t}"
        :: "r"(a), "r"(parity) : "memory");
}
DINL void bulk_g2s(uint32_t dst, const void* src, uint32_t bytes, uint32_t mbar) {
    asm volatile(
        "cp.async.bulk.shared::cta.global.mbarrier::complete_tx::bytes [%0], [%1], %2, [%3];"
        :: "r"(dst), "l"(src), "r"(bytes), "r"(mbar) : "memory");
}

DINL uint32_t sw64(uint32_t off) { return off ^ ((off >> 3) & 0x30); }
DINL float tanh_ap(float x) {
    float y;
    asm("tanh.approx.f32 %0, %1;" : "=f"(y) : "f"(x));
    return y;
}
DINL float fast_sigmoid(float x) { return __fmaf_rn(tanh_ap(0.5f * x), 0.5f, 0.5f); }

// ============================================================================
// Prep kernels (arch-independent, float4 vectorized, SW64 64B-row layout)
// ============================================================================

__global__ void pack_A(const float* __restrict__ x, const float* __restrict__ h) {
    int idx = blockIdx.x * blockDim.x + threadIdx.x;
    int e = idx * 4;
    if (e >= B_SZ * KDIM) return;
    int m = e >> 10, k = e & 1023;
    const float* src = (k < 512) ? (x + m * 512 + k) : (h + m * 512 + (k - 512));
    float4 v = *reinterpret_cast<const float4*>(src);
    __half2 h0 = __floats2half2_rn(v.x, v.y);
    __half2 h1 = __floats2half2_rn(v.z, v.w);
    uint2 hv;
    hv.x = *reinterpret_cast<uint32_t*>(&h0);
    hv.y = *reinterpret_cast<uint32_t*>(&h1);
    int mt = m >> 7, r = m & 127, kc = k >> 5, cc = k & 31;
    uint32_t off = sw64((uint32_t)(r * 64 + cc * 2));
    *reinterpret_cast<uint2*>(reinterpret_cast<char*>(&g_A[mt][kc][0]) + off) = hv;
}

__global__ void pack_W(const float* __restrict__ Wx0, const float* __restrict__ Wx1,
                       const float* __restrict__ Wx2, const float* __restrict__ Wx3,
                       const float* __restrict__ Wh0, const float* __restrict__ Wh1,
                       const float* __restrict__ Wh2, const float* __restrict__ Wh3) {
    int idx = blockIdx.x * blockDim.x + threadIdx.x;
    int e = idx * 4;
    if (e >= 4 * HIDN * KDIM) return;
    int g = e >> 19;
    int rem = e & ((1 << 19) - 1);
    int j = rem >> 10, k = rem & 1023;
    const float* Wx = (g == 0) ? Wx0 : (g == 1) ? Wx1 : (g == 2) ? Wx2 : Wx3;
    const float* Wh = (g == 0) ? Wh0 : (g == 1) ? Wh1 : (g == 2) ? Wh2 : Wh3;
    const float* src = (k < 512) ? (Wx + j * 512 + k) : (Wh + j * 512 + (k - 512));
    float4 v = *reinterpret_cast<const float4*>(src);
    __half2 h0 = __floats2half2_rn(v.x, v.y);
    __half2 h1 = __floats2half2_rn(v.z, v.w);
    uint2 hv;
    hv.x = *reinterpret_cast<uint32_t*>(&h0);
    hv.y = *reinterpret_cast<uint32_t*>(&h1);
    int nblk = j >> 6;
    int row = g * 64 + (j & 63);
    int kc = k >> 5, cc = k & 31;
    uint32_t off = sw64((uint32_t)(row * 64 + cc * 2));
    *reinterpret_cast<uint2*>(reinterpret_cast<char*>(&g_W[nblk][kc][0]) + off) = hv;
}

__global__ void pack_bias(const float* __restrict__ bx0, const float* __restrict__ bx1,
                          const float* __restrict__ bx2, const float* __restrict__ bx3,
                          const float* __restrict__ bh0, const float* __restrict__ bh1,
                          const float* __restrict__ bh2, const float* __restrict__ bh3) {
    int t = blockIdx.x * blockDim.x + threadIdx.x;
    if (t >= 4 * HIDN) return;
    int g = t >> 9, j = t & 511;
    const float* bx = (g == 0) ? bx0 : (g == 1) ? bx1 : (g == 2) ? bx2 : bx3;
    const float* bh = (g == 0) ? bh0 : (g == 1) ? bh1 : (g == 2) ? bh2 : bh3;
    g_bias[t] = bx[j] + bh[j];
}

// ============================================================================
// tcgen05 path (compiles only on sm_103a/sm_100a PTX targets)
// ============================================================================
#if TC_OK

constexpr uint32_t MMA_IDESC = (8u << 24) | ((MMA_N / 8) << 17) | (1u << 4);
// SW64: layout_type=4, version=1 (Blackwell), SBO=32, LBO=1
constexpr uint64_t SMEM_DESC_BASE_SW64 =
    (uint64_t(4) << 61) | (uint64_t(1) << 46) | (uint64_t(32) << 32) | (uint64_t(1) << 16);

DINL uint64_t make_desc(uint32_t smem_addr) {
    return SMEM_DESC_BASE_SW64 | ((uint64_t)(smem_addr >> 4) & 0x3FFF);
}
DINL void mma_f16_ss(uint32_t d, uint64_t a, uint64_t b, uint32_t idesc, uint32_t en) {
    asm volatile(
        "{\n\t.reg .pred p;\n\t"
        "setp.ne.u32 p, %4, 0;\n\t"
        "tcgen05.mma.cta_group::1.kind::f16 [%0], %1, %2, %3, {%5, %5, %5, %5}, p;\n\t}"
        :: "r"(d), "l"(a), "l"(b), "r"(idesc), "r"(en), "r"(0u) : "memory");
}
#define TC_ALLOC(sm, n)   asm volatile("tcgen05.alloc.cta_group::1.sync.aligned.shared::cta.b32 [%0], %1;" :: "r"(sm), "r"(n) : "memory")
#define TC_DEALLOC(t, n)  asm volatile("tcgen05.dealloc.cta_group::1.sync.aligned.b32 %0, %1;" :: "r"(t), "r"(n))
#define TC_RELINQ()       asm volatile("tcgen05.relinquish_alloc_permit.cta_group::1.sync.aligned;")
#define TC_COMMIT(mb)     asm volatile("tcgen05.commit.cta_group::1.mbarrier::arrive::one.shared::cluster.b64 [%0];" :: "r"(mb) : "memory")
#define TC_FENCE_AFTER()  asm volatile("tcgen05.fence::after_thread_sync;" ::: "memory")
#define TC_FENCE_BEFORE() asm volatile("tcgen05.fence::before_thread_sync;" ::: "memory")
#define TC_WAIT_LD()      asm volatile("tcgen05.wait::ld.sync.aligned;" ::: "memory")

#define TC_LD_X16(r, addr) \
    asm volatile( \
        "tcgen05.ld.sync.aligned.32x32b.x16.b32 " \
        "{%0, %1, %2, %3, %4, %5, %6, %7, %8, %9, %10, %11, %12, %13, %14, %15}, [%16];" \
        : "=r"((r)[0]), "=r"((r)[1]), "=r"((r)[2]), "=r"((r)[3]), \
          "=r"((r)[4]), "=r"((r)[5]), "=r"((r)[6]), "=r"((r)[7]), \
          "=r"((r)[8]), "=r"((r)[9]), "=r"((r)[10]), "=r"((r)[11]), \
          "=r"((r)[12]), "=r"((r)[13]), "=r"((r)[14]), "=r"((r)[15]) \
        : "r"(addr))
#endif // TC_OK

__global__ void __launch_bounds__(TC_THREADS, 1)
lstm_tc(const float* __restrict__ c_in, float* __restrict__ out) {
#if TC_OK
    extern __shared__ char smem[];
    const uint32_t sb = smem_u32(smem);
    const int tid  = threadIdx.x;
    const int wid  = tid >> 5;
    const int lane = tid & 31;

    // CTA's 4 items share one nblk (4 | 64): item = nblk*64 + mpair.
    const int item0 = blockIdx.x * ITEMS;
    const int nblk  = item0 >> 6;
    const int c0    = nblk * 64;

    const uint32_t full_bar0  = sb + 64;    // 4 bars, tx-based
    const uint32_t empty_bar0 = sb + 128;   // 4 bars, count 1
    const uint32_t done_bar   = sb + 192;   // count 1, completion per tile
    const uint32_t epi_bar    = sb + 200;   // count 16, completion per tile

    if (wid == 0) { TC_ALLOC(sb, 512); TC_RELINQ(); }
    if (tid == 0) {
        for (int s = 0; s < TCS; s++) {
            mbar_init(full_bar0 + s * 8, 1);
            mbar_init(empty_bar0 + s * 8, 1);
        }
        mbar_init(done_bar, 1);
        mbar_init(epi_bar, 16);
    }
    float* bias_s = reinterpret_cast<float*>(smem + 1024);
    if (tid < 256) bias_s[tid] = g_bias[(tid >> 6) * HIDN + c0 + (tid & 63)];
    __syncthreads();

    uint32_t tmem;
    asm volatile("ld.shared.b32 %0, [%1];" : "=r"(tmem) : "r"(sb));

    if (wid == 16) {
        // ---- Producer (lane 0): continuous chunk stream over all tiles ----
        if (lane == 0) {
            const char* Bbase = reinterpret_cast<const char*>(&g_W[nblk][0][0]);
            for (int t = 0; t < ITEMS; t++) {
                const int mp = (item0 + t) & 63;
                const char* A0base = reinterpret_cast<const char*>(&g_A[mp * 2 + 0][0][0]);
                const char* A1base = reinterpret_cast<const char*>(&g_A[mp * 2 + 1][0][0]);
                for (int ch = 0; ch < N_CHUNKS; ch++) {
                    const int g = t * N_CHUNKS + ch;
                    const int s = g & (TCS - 1);
                    if (g >= TCS) mbar_wait(empty_bar0 + s * 8, ((g - TCS) >> 2) & 1);
                    mbar_expect_tx(full_bar0 + s * 8, STAGE_BYTES);
                    uint32_t st = sb + SMEM_HDR + s * STAGE_BYTES;
                    bulk_g2s(st,               A0base + ch * A_BYTES, A_BYTES, full_bar0 + s * 8);
                    bulk_g2s(st + A_BYTES,     A1base + ch * A_BYTES, A_BYTES, full_bar0 + s * 8);
                    bulk_g2s(st + 2 * A_BYTES, Bbase  + ch * B_BYTES, B_BYTES, full_bar0 + s * 8);
                }
            }
        }
    } else if (wid == 17) {
        // ---- MMA issuer (lane 0) ----
        if (lane == 0) {
            for (int t = 0; t < ITEMS; t++) {
                // D cols are reused across tiles: wait for previous epilogue
                // to finish reading before the en=0 overwrite.
                if (t > 0) mbar_wait(epi_bar, (t - 1) & 1);
                for (int ch = 0; ch < N_CHUNKS; ch++) {
                    const int g = t * N_CHUNKS + ch;
                    const int s = g & (TCS - 1);
                    mbar_wait(full_bar0 + s * 8, (g >> 2) & 1);
                    uint32_t st = sb + SMEM_HDR + s * STAGE_BYTES;
                    uint64_t ad0 = make_desc(st);
                    uint64_t ad1 = make_desc(st + A_BYTES);
                    uint64_t bd  = make_desc(st + 2 * A_BYTES);
                    const uint32_t en = (ch == 0) ? 0u : 1u;
                    mma_f16_ss(tmem,       ad0 + 0, bd + 0, MMA_IDESC, en);
                    mma_f16_ss(tmem,       ad0 + 2, bd + 2, MMA_IDESC, 1u);
                    mma_f16_ss(tmem + 256, ad1 + 0, bd + 0, MMA_IDESC, en);
                    mma_f16_ss(tmem + 256, ad1 + 2, bd + 2, MMA_IDESC, 1u);
                    TC_COMMIT(empty_bar0 + s * 8);
                }
                TC_COMMIT(done_bar);
            }
        }
    } else {
        // ---- 16 epilogue warps: warp w -> subpartition sp=w&3, m-tile
        // mt=(w>>2)&1, column half=(w>>3)&1, two 16-col blocks per half.
        const int sp = wid & 3, mt = (wid >> 2) & 1, half = (wid >> 3) & 1;
        const int r = sp * 32 + lane;
        const uint32_t dbase = tmem + mt * 256;

        for (int t = 0; t < ITEMS; t++) {
            mbar_wait(done_bar, t & 1);
            TC_FENCE_AFTER();

            const int mp = (item0 + t) & 63;
            const int mrow = (mp * 2 + mt) * TILE_M + r;
            const float* crow = c_in + (size_t)mrow * HIDN + c0;
            float*       hrow = out + (size_t)mrow * HIDN + c0;
            float*       orow = out + (size_t)B_SZ * HIDN + (size_t)mrow * HIDN + c0;

            #pragma unroll
            for (int jb = 0; jb < 2; jb++) {
                const int j = half * 32 + jb * 16;
                uint32_t ri[16], rg[16], rf[16], ro[16];
                TC_LD_X16(ri, dbase + 0 + j);
                TC_LD_X16(rg, dbase + 64 + j);
                TC_LD_X16(rf, dbase + 128 + j);
                TC_LD_X16(ro, dbase + 192 + j);
                TC_WAIT_LD();

                float cv[16];
                #pragma unroll
                for (int q = 0; q < 4; q++)
                    *reinterpret_cast<float4*>(&cv[q * 4]) =
                        *reinterpret_cast<const float4*>(crow + j + q * 4);

                // Compute in place: ri -> h_new bits, rg -> c_new bits.
                #pragma unroll
                for (int q = 0; q < 16; q++) {
                    const int jj = j + q;
                    float iv = fast_sigmoid(__uint_as_float(ri[q]) + bias_s[jj]);
                    float gv = tanh_ap(__uint_as_float(rg[q]) + bias_s[64 + jj]);
                    float fv = fast_sigmoid(__uint_as_float(rf[q]) + bias_s[128 + jj]);
                    float ov = fast_sigmoid(__uint_as_float(ro[q]) + bias_s[192 + jj]);
                    float c2 = fv * cv[q] + iv * gv;
                    rg[q] = __float_as_uint(c2);
                    ri[q] = __float_as_uint(ov * tanh_ap(c2));
                }
                #pragma unroll
                for (int q = 0; q < 4; q++) {
                    *reinterpret_cast<float4*>(hrow + j + q * 4) =
                        *reinterpret_cast<const float4*>(&ri[q * 4]);
                    *reinterpret_cast<float4*>(orow + j + q * 4) =
                        *reinterpret_cast<const float4*>(&rg[q * 4]);
                }
            }
            // All D reads for this tile are drained; release D for tile t+1.
            TC_FENCE_BEFORE();
            if (lane == 0) mbar_arrive(epi_bar);
        }
    }

    __syncthreads();
    if (wid == 0) { TC_DEALLOC(tmem, 512); }
#endif // TC_OK
}

// ============================================================================
// Fallback (plain sm_103 cubin only; never selected on the 'a' builds the
// bench has loaded every round): simple SIMT GEMM over the packed tiles.
// ============================================================================

__global__ void lstm_fb(const float* __restrict__ c_in, float* __restrict__ out) {
    int gidx = blockIdx.x * blockDim.x + threadIdx.x;   // 0 .. B_SZ*HIDN-1
    if (gidx >= B_SZ * HIDN) return;
    int m = gidx >> 9;
    int jcol = gidx & 511;
    int nblk = jcol >> 6, jj = jcol & 63;
    int mt = m >> 7, r = m & 127;

    float acc[4] = {0.f, 0.f, 0.f, 0.f};
    for (int kc = 0; kc < N_CHUNKS; kc++) {
        const __half* At = &g_A[mt][kc][0];
        const __half* Wt = &g_W[nblk][kc][0];
        for (int cc = 0; cc < K_CHUNK; cc++) {
            float av = __half2float(*reinterpret_cast<const __half*>(
                reinterpret_cast<const char*>(At) + sw64((uint32_t)(r * 64 + cc * 2))));
            #pragma unroll
            for (int g = 0; g < 4; g++) {
                int row = g * 64 + jj;
                float wv = __half2float(*reinterpret_cast<const __half*>(
                    reinterpret_cast<const char*>(Wt) + sw64((uint32_t)(row * 64 + cc * 2))));
                acc[g] += av * wv;
            }
        }
    }
    int c0 = nblk * 64;
    float iv = fast_sigmoid(acc[0] + g_bias[c0 + jj]);
    float gv = tanh_ap     (acc[1] + g_bias[512 + c0 + jj]);
    float fv = fast_sigmoid(acc[2] + g_bias[1024 + c0 + jj]);
    float ov = fast_sigmoid(acc[3] + g_bias[1536 + c0 + jj]);
    float cv = c_in[m * HIDN + jcol];
    float cn = fv * cv + iv * gv;
    out[m * HIDN + jcol] = ov * tanh_ap(cn);
    out[B_SZ * HIDN + m * HIDN + jcol] = cn;
}

// ============================================================================
// Launch
// ============================================================================

extern "C" void kernel_launch(void* const* d_in, const int* in_sizes, int n_in,
                              void* d_out, int out_size) {
    const float* x = (const float*)d_in[0];
    const float* h = (const float*)d_in[1];
    const float* c = (const float*)d_in[2];
    // gate order in packed layout: 0=i, 1=g, 2=f, 3=o
    const float* Wxi = (const float*)d_in[3];  const float* bxi = (const float*)d_in[4];
    const float* Wxo = (const float*)d_in[5];  const float* bxo = (const float*)d_in[6];
    const float* Wxf = (const float*)d_in[7];  const float* bxf = (const float*)d_in[8];
    const float* Wxg = (const float*)d_in[9];  const float* bxg = (const float*)d_in[10];
    const float* Whi = (const float*)d_in[11]; const float* bhi = (const float*)d_in[12];
    const float* Who = (const float*)d_in[13]; const float* bho = (const float*)d_in[14];
    const float* Whf = (const float*)d_in[15]; const float* bhf = (const float*)d_in[16];
    const float* Whg = (const float*)d_in[17]; const float* bhg = (const float*)d_in[18];

    pack_A<<<(B_SZ * KDIM / 4 + 255) / 256, 256>>>(x, h);
    pack_W<<<(4 * HIDN * KDIM / 4 + 255) / 256, 256>>>(Wxi, Wxg, Wxf, Wxo, Whi, Whg, Whf, Who);
    pack_bias<<<8, 256>>>(bxi, bxg, bxf, bxo, bhi, bhg, bhf, bho);

    // Host-side path selection: the tcgen05 kernel only has a real body when
    // the loaded cubin came from a 103a-feature gencode pass.
    cudaFuncAttributes attr;
    cudaFuncGetAttributes(&attr, lstm_tc);
    const bool use_tc = attr.numRegs > 40;

    if (use_tc) {
        cudaFuncSetAttribute(lstm_tc, cudaFuncAttributeMaxDynamicSharedMemorySize, SMEM_TOTAL_TC);
        lstm_tc<<<GRID_X, TC_THREADS, SMEM_TOTAL_TC>>>(c, (float*)d_out);
    } else {
        lstm_fb<<<(B_SZ * HIDN + 255) / 256, 256>>>(c, (float*)d_out);
    }
}

// round 16
// speedup vs baseline: 1.0836x; 1.0836x over previous
#include <cuda_runtime.h>
#include <cuda_fp16.h>
#include <cstdint>

// ============================================================================
// LSTMCell: gates = [x|h] @ [Wx|Wh]^T + b, then elementwise LSTM math.
// M=16384, N=2048 (4 gates x 512), K=1024.  fp16 tcgen05 GEMM, fp32 accum.
//
// Live path: tcgen05 (sm_103a gencode), PERSISTENT CTAs on ALL 148 SMs:
//   512 work items (nblk, m-pair), CTA bx handles it = bx, bx+148, ...
//   Producer warp (16) + MMA warp (17) stream items back-to-back through a
//   4-stage / 32KB pipeline; 16 epilogue warps process tile t's TMEM D while
//   tile t+1's operands are delivered. Wall model: per-SM NoC delivery share
//   (~30 B/cyc/SM) -> spreading the same bytes over 148 instead of 128 SMs.
//   CTA tile = 2 m-tiles x 256 N (W-chunk reuse x2 -> 524 MB operands).
// ============================================================================

#define DINL __device__ __forceinline__

#if defined(__CUDA_ARCH__)
# if defined(__CUDA_ARCH_FEAT_SM103_ALL) || defined(__CUDA_ARCH_FEAT_SM100_ALL)
#  define TC_OK 1
# else
#  define TC_OK 0
# endif
#else
# define TC_OK 0
#endif

constexpr int B_SZ   = 16384;
constexpr int HIDN   = 512;
constexpr int KDIM   = 1024;
constexpr int TILE_M = 128;
constexpr int MMA_N  = 256;               // 4 gates * 64 hidden cols
constexpr int K_CHUNK = 32;               // fp16 elems per chunk (64 bytes/row)
constexpr int N_CHUNKS = KDIM / K_CHUNK;  // 32
constexpr int A_BYTES = TILE_M * 64;      // 8192 per m-tile chunk
constexpr int B_BYTES = MMA_N * 64;       // 16384
constexpr int STAGE_BYTES = 2 * A_BYTES + B_BYTES; // 32768
constexpr int TCS = 4;                    // 4 stages = 128KB
constexpr int N_ITEMS = 512;              // 8 nblk x 64 m-pairs
constexpr int GRID_X = 148;               // persistent, all SMs

constexpr int SMEM_HDR = 2048;
constexpr int SMEM_TOTAL_TC = SMEM_HDR + TCS * STAGE_BYTES;   // 133120
constexpr int TC_THREADS = 576;           // 16 epi warps + producer + mma

// Pre-packed operands (device globals; no runtime allocation).
__device__ __align__(1024) __half g_A[B_SZ / TILE_M][N_CHUNKS][TILE_M * K_CHUNK];
__device__ __align__(1024) __half g_W[8][N_CHUNKS][MMA_N * K_CHUNK];
__device__ float g_bias[4 * HIDN];

DINL uint32_t smem_u32(const void* p) {
    uint32_t a;
    asm("{ .reg .u64 t; cvta.to.shared.u64 t, %1; cvt.u32.u64 %0, t; }" : "=r"(a) : "l"(p));
    return a;
}
DINL void mbar_init(uint32_t a, uint32_t cnt) {
    asm volatile("mbarrier.init.shared.b64 [%0], %1;" :: "r"(a), "r"(cnt) : "memory");
}
DINL void mbar_expect_tx(uint32_t a, uint32_t bytes) {
    asm volatile("mbarrier.arrive.expect_tx.shared.b64 _, [%0], %1;" :: "r"(a), "r"(bytes) : "memory");
}
DINL void mbar_arrive(uint32_t a) {
    asm volatile("mbarrier.arrive.shared.b64 _, [%0];" :: "r"(a) : "memory");
}
DINL void mbar_wait(uint32_t a, uint32_t parity) {
    asm volatile(
        "{\n\t.reg .pred P;\n\t"
        "W_%=:\n\t"
        "mbarrier.try_wait.parity.acquire.cta.shared::cta.b64 P, [%0], %1, 0x989680;\n\t"
        "@P bra.uni D_%=;\n\t"
        "bra.uni W_%=;\n\t"
        "D_%=:\n\t}"
        :: "r"(a), "r"(parity) : "memory");
}
DINL void bulk_g2s(uint32_t dst, const void* src, uint32_t bytes, uint32_t mbar) {
    asm volatile(
        "cp.async.bulk.shared::cta.global.mbarrier::complete_tx::bytes [%0], [%1], %2, [%3];"
        :: "r"(dst), "l"(src), "r"(bytes), "r"(mbar) : "memory");
}

DINL uint32_t sw64(uint32_t off) { return off ^ ((off >> 3) & 0x30); }
DINL float tanh_ap(float x) {
    float y;
    asm("tanh.approx.f32 %0, %1;" : "=f"(y) : "f"(x));
    return y;
}
DINL float fast_sigmoid(float x) { return __fmaf_rn(tanh_ap(0.5f * x), 0.5f, 0.5f); }

// ============================================================================
// Fused prep kernel (A + W + bias in one launch; SW64 64B-row layout)
// ============================================================================

constexpr int PK_A = B_SZ * KDIM / 4;          // 4,194,304 threads
constexpr int PK_W = 4 * HIDN * KDIM / 4;      // 524,288 threads
constexpr int PK_B = 4 * HIDN;                 // 2,048 threads
constexpr int PK_TOTAL = PK_A + PK_W + PK_B;

__global__ void pack_all(const float* __restrict__ x, const float* __restrict__ h,
                         const float* __restrict__ Wx0, const float* __restrict__ Wx1,
                         const float* __restrict__ Wx2, const float* __restrict__ Wx3,
                         const float* __restrict__ Wh0, const float* __restrict__ Wh1,
                         const float* __restrict__ Wh2, const float* __restrict__ Wh3,
                         const float* __restrict__ bx0, const float* __restrict__ bx1,
                         const float* __restrict__ bx2, const float* __restrict__ bx3,
                         const float* __restrict__ bh0, const float* __restrict__ bh1,
                         const float* __restrict__ bh2, const float* __restrict__ bh3) {
    int idx = blockIdx.x * blockDim.x + threadIdx.x;
    if (idx < PK_A) {
        int e = idx * 4;
        int m = e >> 10, k = e & 1023;
        const float* src = (k < 512) ? (x + m * 512 + k) : (h + m * 512 + (k - 512));
        float4 v = *reinterpret_cast<const float4*>(src);
        __half2 h0 = __floats2half2_rn(v.x, v.y);
        __half2 h1 = __floats2half2_rn(v.z, v.w);
        uint2 hv;
        hv.x = *reinterpret_cast<uint32_t*>(&h0);
        hv.y = *reinterpret_cast<uint32_t*>(&h1);
        int mt = m >> 7, r = m & 127, kc = k >> 5, cc = k & 31;
        uint32_t off = sw64((uint32_t)(r * 64 + cc * 2));
        *reinterpret_cast<uint2*>(reinterpret_cast<char*>(&g_A[mt][kc][0]) + off) = hv;
    } else if (idx < PK_A + PK_W) {
        int e = (idx - PK_A) * 4;
        int g = e >> 19;
        int rem = e & ((1 << 19) - 1);
        int j = rem >> 10, k = rem & 1023;
        const float* Wx = (g == 0) ? Wx0 : (g == 1) ? Wx1 : (g == 2) ? Wx2 : Wx3;
        const float* Wh = (g == 0) ? Wh0 : (g == 1) ? Wh1 : (g == 2) ? Wh2 : Wh3;
        const float* src = (k < 512) ? (Wx + j * 512 + k) : (Wh + j * 512 + (k - 512));
        float4 v = *reinterpret_cast<const float4*>(src);
        __half2 h0 = __floats2half2_rn(v.x, v.y);
        __half2 h1 = __floats2half2_rn(v.z, v.w);
        uint2 hv;
        hv.x = *reinterpret_cast<uint32_t*>(&h0);
        hv.y = *reinterpret_cast<uint32_t*>(&h1);
        int nblk = j >> 6;
        int row = g * 64 + (j & 63);
        int kc = k >> 5, cc = k & 31;
        uint32_t off = sw64((uint32_t)(row * 64 + cc * 2));
        *reinterpret_cast<uint2*>(reinterpret_cast<char*>(&g_W[nblk][kc][0]) + off) = hv;
    } else if (idx < PK_TOTAL) {
        int t = idx - PK_A - PK_W;
        int g = t >> 9, j = t & 511;
        const float* bx = (g == 0) ? bx0 : (g == 1) ? bx1 : (g == 2) ? bx2 : bx3;
        const float* bh = (g == 0) ? bh0 : (g == 1) ? bh1 : (g == 2) ? bh2 : bh3;
        g_bias[t] = bx[j] + bh[j];
    }
}

// ============================================================================
// tcgen05 path (compiles only on sm_103a/sm_100a PTX targets)
// ============================================================================
#if TC_OK

constexpr uint32_t MMA_IDESC = (8u << 24) | ((MMA_N / 8) << 17) | (1u << 4);
// SW64: layout_type=4, version=1 (Blackwell), SBO=32, LBO=1
constexpr uint64_t SMEM_DESC_BASE_SW64 =
    (uint64_t(4) << 61) | (uint64_t(1) << 46) | (uint64_t(32) << 32) | (uint64_t(1) << 16);

DINL uint64_t make_desc(uint32_t smem_addr) {
    return SMEM_DESC_BASE_SW64 | ((uint64_t)(smem_addr >> 4) & 0x3FFF);
}
DINL void mma_f16_ss(uint32_t d, uint64_t a, uint64_t b, uint32_t idesc, uint32_t en) {
    asm volatile(
        "{\n\t.reg .pred p;\n\t"
        "setp.ne.u32 p, %4, 0;\n\t"
        "tcgen05.mma.cta_group::1.kind::f16 [%0], %1, %2, %3, {%5, %5, %5, %5}, p;\n\t}"
        :: "r"(d), "l"(a), "l"(b), "r"(idesc), "r"(en), "r"(0u) : "memory");
}
#define TC_ALLOC(sm, n)   asm volatile("tcgen05.alloc.cta_group::1.sync.aligned.shared::cta.b32 [%0], %1;" :: "r"(sm), "r"(n) : "memory")
#define TC_DEALLOC(t, n)  asm volatile("tcgen05.dealloc.cta_group::1.sync.aligned.b32 %0, %1;" :: "r"(t), "r"(n))
#define TC_RELINQ()       asm volatile("tcgen05.relinquish_alloc_permit.cta_group::1.sync.aligned;")
#define TC_COMMIT(mb)     asm volatile("tcgen05.commit.cta_group::1.mbarrier::arrive::one.shared::cluster.b64 [%0];" :: "r"(mb) : "memory")
#define TC_FENCE_AFTER()  asm volatile("tcgen05.fence::after_thread_sync;" ::: "memory")
#define TC_FENCE_BEFORE() asm volatile("tcgen05.fence::before_thread_sync;" ::: "memory")
#define TC_WAIT_LD()      asm volatile("tcgen05.wait::ld.sync.aligned;" ::: "memory")

#define TC_LD_X16(r, addr) \
    asm volatile( \
        "tcgen05.ld.sync.aligned.32x32b.x16.b32 " \
        "{%0, %1, %2, %3, %4, %5, %6, %7, %8, %9, %10, %11, %12, %13, %14, %15}, [%16];" \
        : "=r"((r)[0]), "=r"((r)[1]), "=r"((r)[2]), "=r"((r)[3]), \
          "=r"((r)[4]), "=r"((r)[5]), "=r"((r)[6]), "=r"((r)[7]), \
          "=r"((r)[8]), "=r"((r)[9]), "=r"((r)[10]), "=r"((r)[11]), \
          "=r"((r)[12]), "=r"((r)[13]), "=r"((r)[14]), "=r"((r)[15]) \
        : "r"(addr))
#endif // TC_OK

__global__ void __launch_bounds__(TC_THREADS, 1)
lstm_tc(const float* __restrict__ c_in, float* __restrict__ out) {
#if TC_OK
    extern __shared__ char smem[];
    const uint32_t sb = smem_u32(smem);
    const int tid  = threadIdx.x;
    const int wid  = tid >> 5;
    const int lane = tid & 31;
    const int bx   = blockIdx.x;

    // Work items strided across persistent CTAs: it = bx, bx+148, ...
    const int n_items = 3 + (bx < (N_ITEMS - 3 * GRID_X));   // 512 = 3*148 + 68

    const uint32_t full_bar0  = sb + 64;    // 4 bars, tx-based
    const uint32_t empty_bar0 = sb + 128;   // 4 bars, count 1
    const uint32_t done_bar   = sb + 192;   // count 1, completion per tile
    const uint32_t epi_bar    = sb + 200;   // count 16, completion per tile

    if (wid == 0) { TC_ALLOC(sb, 512); TC_RELINQ(); }
    if (tid == 0) {
        for (int s = 0; s < TCS; s++) {
            mbar_init(full_bar0 + s * 8, 1);
            mbar_init(empty_bar0 + s * 8, 1);
        }
        mbar_init(done_bar, 1);
        mbar_init(epi_bar, 16);
    }
    __syncthreads();

    uint32_t tmem;
    asm volatile("ld.shared.b32 %0, [%1];" : "=r"(tmem) : "r"(sb));

    if (wid == 16) {
        // ---- Producer (lane 0): continuous chunk stream over all items ----
        if (lane == 0) {
            for (int t = 0; t < n_items; t++) {
                const int item = bx + t * GRID_X;
                const int nblk = item >> 6;
                const int mp   = item & 63;
                const char* A0base = reinterpret_cast<const char*>(&g_A[mp * 2 + 0][0][0]);
                const char* A1base = reinterpret_cast<const char*>(&g_A[mp * 2 + 1][0][0]);
                const char* Bbase  = reinterpret_cast<const char*>(&g_W[nblk][0][0]);
                for (int ch = 0; ch < N_CHUNKS; ch++) {
                    const int g = t * N_CHUNKS + ch;
                    const int s = g & (TCS - 1);
                    if (g >= TCS) mbar_wait(empty_bar0 + s * 8, ((g - TCS) >> 2) & 1);
                    mbar_expect_tx(full_bar0 + s * 8, STAGE_BYTES);
                    uint32_t st = sb + SMEM_HDR + s * STAGE_BYTES;
                    bulk_g2s(st,               A0base + ch * A_BYTES, A_BYTES, full_bar0 + s * 8);
                    bulk_g2s(st + A_BYTES,     A1base + ch * A_BYTES, A_BYTES, full_bar0 + s * 8);
                    bulk_g2s(st + 2 * A_BYTES, Bbase  + ch * B_BYTES, B_BYTES, full_bar0 + s * 8);
                }
            }
        }
    } else if (wid == 17) {
        // ---- MMA issuer (lane 0) ----
        if (lane == 0) {
            for (int t = 0; t < n_items; t++) {
                // D cols are reused across tiles: wait for previous epilogue
                // to finish reading before the en=0 overwrite.
                if (t > 0) mbar_wait(epi_bar, (t - 1) & 1);
                for (int ch = 0; ch < N_CHUNKS; ch++) {
                    const int g = t * N_CHUNKS + ch;
                    const int s = g & (TCS - 1);
                    mbar_wait(full_bar0 + s * 8, (g >> 2) & 1);
                    uint32_t st = sb + SMEM_HDR + s * STAGE_BYTES;
                    uint64_t ad0 = make_desc(st);
                    uint64_t ad1 = make_desc(st + A_BYTES);
                    uint64_t bd  = make_desc(st + 2 * A_BYTES);
                    const uint32_t en = (ch == 0) ? 0u : 1u;
                    mma_f16_ss(tmem,       ad0 + 0, bd + 0, MMA_IDESC, en);
                    mma_f16_ss(tmem,       ad0 + 2, bd + 2, MMA_IDESC, 1u);
                    mma_f16_ss(tmem + 256, ad1 + 0, bd + 0, MMA_IDESC, en);
                    mma_f16_ss(tmem + 256, ad1 + 2, bd + 2, MMA_IDESC, 1u);
                    TC_COMMIT(empty_bar0 + s * 8);
                }
                TC_COMMIT(done_bar);
            }
        }
    } else {
        // ---- 16 epilogue warps: warp w -> subpartition sp=w&3, m-tile
        // mt=(w>>2)&1, column half=(w>>3)&1, two 16-col blocks per half.
        const int sp = wid & 3, mt = (wid >> 2) & 1, half = (wid >> 3) & 1;
        const int r = sp * 32 + lane;
        const uint32_t dbase = tmem + mt * 256;

        for (int t = 0; t < n_items; t++) {
            mbar_wait(done_bar, t & 1);
            TC_FENCE_AFTER();

            const int item = bx + t * GRID_X;
            const int nblk = item >> 6;
            const int mp   = item & 63;
            const int c0   = nblk * 64;
            const int mrow = (mp * 2 + mt) * TILE_M + r;
            const float* crow = c_in + (size_t)mrow * HIDN + c0;
            float*       hrow = out + (size_t)mrow * HIDN + c0;
            float*       orow = out + (size_t)B_SZ * HIDN + (size_t)mrow * HIDN + c0;

            #pragma unroll
            for (int jb = 0; jb < 2; jb++) {
                const int j = half * 32 + jb * 16;
                uint32_t ri[16], rg[16], rf[16], ro[16];
                TC_LD_X16(ri, dbase + 0 + j);
                TC_LD_X16(rg, dbase + 64 + j);
                TC_LD_X16(rf, dbase + 128 + j);
                TC_LD_X16(ro, dbase + 192 + j);
                TC_WAIT_LD();

                float cv[16];
                #pragma unroll
                for (int q = 0; q < 4; q++)
                    *reinterpret_cast<float4*>(&cv[q * 4]) =
                        *reinterpret_cast<const float4*>(crow + j + q * 4);

                // Bias straight from global (L1/L2-hot, 2KB table).
                const float* bi = g_bias + c0 + j;
                // Compute in place: ri -> h_new bits, rg -> c_new bits.
                #pragma unroll
                for (int q = 0; q < 16; q++) {
                    float iv = fast_sigmoid(__uint_as_float(ri[q]) + bi[q]);
                    float gv = tanh_ap(__uint_as_float(rg[q]) + bi[512 + q]);
                    float fv = fast_sigmoid(__uint_as_float(rf[q]) + bi[1024 + q]);
                    float ov = fast_sigmoid(__uint_as_float(ro[q]) + bi[1536 + q]);
                    float c2 = fv * cv[q] + iv * gv;
                    rg[q] = __float_as_uint(c2);
                    ri[q] = __float_as_uint(ov * tanh_ap(c2));
                }
                #pragma unroll
                for (int q = 0; q < 4; q++) {
                    *reinterpret_cast<float4*>(hrow + j + q * 4) =
                        *reinterpret_cast<const float4*>(&ri[q * 4]);
                    *reinterpret_cast<float4*>(orow + j + q * 4) =
                        *reinterpret_cast<const float4*>(&rg[q * 4]);
                }
            }
            // All D reads for this tile are drained; release D for tile t+1.
            TC_FENCE_BEFORE();
            if (lane == 0) mbar_arrive(epi_bar);
        }
    }

    __syncthreads();
    if (wid == 0) { TC_DEALLOC(tmem, 512); }
#endif // TC_OK
}

// ============================================================================
// Fallback (plain sm_103 cubin only; never selected on the 'a' builds the
// bench has loaded every round): simple SIMT GEMM over the packed tiles.
// ============================================================================

__global__ void lstm_fb(const float* __restrict__ c_in, float* __restrict__ out) {
    int gidx = blockIdx.x * blockDim.x + threadIdx.x;   // 0 .. B_SZ*HIDN-1
    if (gidx >= B_SZ * HIDN) return;
    int m = gidx >> 9;
    int jcol = gidx & 511;
    int nblk = jcol >> 6, jj = jcol & 63;
    int mt = m >> 7, r = m & 127;

    float acc[4] = {0.f, 0.f, 0.f, 0.f};
    for (int kc = 0; kc < N_CHUNKS; kc++) {
        const __half* At = &g_A[mt][kc][0];
        const __half* Wt = &g_W[nblk][kc][0];
        for (int cc = 0; cc < K_CHUNK; cc++) {
            float av = __half2float(*reinterpret_cast<const __half*>(
                reinterpret_cast<const char*>(At) + sw64((uint32_t)(r * 64 + cc * 2))));
            #pragma unroll
            for (int g = 0; g < 4; g++) {
                int row = g * 64 + jj;
                float wv = __half2float(*reinterpret_cast<const __half*>(
                    reinterpret_cast<const char*>(Wt) + sw64((uint32_t)(row * 64 + cc * 2))));
                acc[g] += av * wv;
            }
        }
    }
    int c0 = nblk * 64;
    float iv = fast_sigmoid(acc[0] + g_bias[c0 + jj]);
    float gv = tanh_ap     (acc[1] + g_bias[512 + c0 + jj]);
    float fv = fast_sigmoid(acc[2] + g_bias[1024 + c0 + jj]);
    float ov = fast_sigmoid(acc[3] + g_bias[1536 + c0 + jj]);
    float cv = c_in[m * HIDN + jcol];
    float cn = fv * cv + iv * gv;
    out[m * HIDN + jcol] = ov * tanh_ap(cn);
    out[B_SZ * HIDN + m * HIDN + jcol] = cn;
}

// ============================================================================
// Launch
// ============================================================================

extern "C" void kernel_launch(void* const* d_in, const int* in_sizes, int n_in,
                              void* d_out, int out_size) {
    const float* x = (const float*)d_in[0];
    const float* h = (const float*)d_in[1];
    const float* c = (const float*)d_in[2];
    // gate order in packed layout: 0=i, 1=g, 2=f, 3=o
    const float* Wxi = (const float*)d_in[3];  const float* bxi = (const float*)d_in[4];
    const float* Wxo = (const float*)d_in[5];  const float* bxo = (const float*)d_in[6];
    const float* Wxf = (const float*)d_in[7];  const float* bxf = (const float*)d_in[8];
    const float* Wxg = (const float*)d_in[9];  const float* bxg = (const float*)d_in[10];
    const float* Whi = (const float*)d_in[11]; const float* bhi = (const float*)d_in[12];
    const float* Who = (const float*)d_in[13]; const float* bho = (const float*)d_in[14];
    const float* Whf = (const float*)d_in[15]; const float* bhf = (const float*)d_in[16];
    const float* Whg = (const float*)d_in[17]; const float* bhg = (const float*)d_in[18];

    pack_all<<<(PK_TOTAL + 255) / 256, 256>>>(
        x, h, Wxi, Wxg, Wxf, Wxo, Whi, Whg, Whf, Who,
        bxi, bxg, bxf, bxo, bhi, bhg, bhf, bho);

    // Host-side path selection: the tcgen05 kernel only has a real body when
    // the loaded cubin came from a 103a-feature gencode pass.
    cudaFuncAttributes attr;
    cudaFuncGetAttributes(&attr, lstm_tc);
    const bool use_tc = attr.numRegs > 40;

    if (use_tc) {
        cudaFuncSetAttribute(lstm_tc, cudaFuncAttributeMaxDynamicSharedMemorySize, SMEM_TOTAL_TC);
        lstm_tc<<<GRID_X, TC_THREADS, SMEM_TOTAL_TC>>>(c, (float*)d_out);
    } else {
        lstm_fb<<<(B_SZ * HIDN + 255) / 256, 256>>>(c, (float*)d_out);
    }
}

// round 17
// speedup vs baseline: 1.1742x; 1.0836x over previous
#include <cuda_runtime.h>
#include <cuda_fp16.h>
#include <cstdint>

// ============================================================================
// LSTMCell: gates = [x|h] @ [Wx|Wh]^T + b, then elementwise LSTM math.
// M=16384, N=2048 (4 gates x 512), K=1024.  fp16 tcgen05 GEMM, fp32 accum.
//
// Live path: tcgen05 cta_group::2 pairs (sm_103a gencode), persistent:
//   296 CTAs = 148 cluster(2) pairs, 2 CTAs/SM. Pair item = 256 m-rows x
//   64 hidden cols (M=256 N=256 K=1024 cg2 MMA). Each CTA streams its A half
//   (8KB/chunk) + its W half (8KB/chunk, HW reads N/2 per CTA) through its
//   OWN 4-stage TMA/mbarrier chain -> two delivery streams per SM (the
//   measured per-CTA chain ceiling ~55-60 GB/s was the wall) at R12's
//   optimal 530 MB operand traffic. D = 256 TMEM cols per CTA.
// ============================================================================

#define DINL __device__ __forceinline__

#if defined(__CUDA_ARCH__)
# if defined(__CUDA_ARCH_FEAT_SM103_ALL) || defined(__CUDA_ARCH_FEAT_SM100_ALL)
#  define TC_OK 1
# else
#  define TC_OK 0
# endif
#else
# define TC_OK 0
#endif

constexpr int B_SZ   = 16384;
constexpr int HIDN   = 512;
constexpr int KDIM   = 1024;
constexpr int TILE_M = 128;
constexpr int MMA_N  = 256;               // 4 gates * 64 hidden cols
constexpr int K_CHUNK = 32;               // fp16 elems per chunk (64 bytes/row)
constexpr int N_CHUNKS = KDIM / K_CHUNK;  // 32
constexpr int A_BYTES = TILE_M * 64;      // 8192: this CTA's A half per chunk
constexpr int WH_BYTES = 128 * 64;        // 8192: this CTA's W half per chunk
constexpr int STAGE_BYTES = A_BYTES + WH_BYTES;   // 16384 per CTA
constexpr int TCS = 4;                    // 4 stages = 64KB per CTA
constexpr int N_ITEMS = 512;              // 8 nblk x 64 m-quads (256 rows)
constexpr int N_PAIRS = 148;
constexpr int GRID_X  = 2 * N_PAIRS;      // 296 CTAs

constexpr int SMEM_HDR = 2048;
constexpr int SMEM_TOTAL_TC = SMEM_HDR + TCS * STAGE_BYTES;   // 67584
constexpr int TC_THREADS = 320;           // 8 epi warps + producer + mma/relay

// Pre-packed operands (device globals; no runtime allocation).
__device__ __align__(1024) __half g_A[B_SZ / TILE_M][N_CHUNKS][TILE_M * K_CHUNK];
__device__ __align__(1024) __half g_W[8][N_CHUNKS][MMA_N * K_CHUNK];
__device__ float g_bias[4 * HIDN];

DINL uint32_t smem_u32(const void* p) {
    uint32_t a;
    asm("{ .reg .u64 t; cvta.to.shared.u64 t, %1; cvt.u32.u64 %0, t; }" : "=r"(a) : "l"(p));
    return a;
}
DINL void mbar_init(uint32_t a, uint32_t cnt) {
    asm volatile("mbarrier.init.shared.b64 [%0], %1;" :: "r"(a), "r"(cnt) : "memory");
}
DINL void mbar_expect_tx(uint32_t a, uint32_t bytes) {
    asm volatile("mbarrier.arrive.expect_tx.shared.b64 _, [%0], %1;" :: "r"(a), "r"(bytes) : "memory");
}
DINL void mbar_arrive(uint32_t a) {
    asm volatile("mbarrier.arrive.shared.b64 _, [%0];" :: "r"(a) : "memory");
}
// Arrive on the same-offset mbarrier in cluster CTA `rank` (via mapa).
DINL void mbar_arrive_cluster(uint32_t local_addr, uint32_t rank) {
    asm volatile(
        "{\n\t.reg .b32 ra;\n\t"
        "mapa.shared::cluster.u32 ra, %0, %1;\n\t"
        "mbarrier.arrive.shared::cluster.b64 _, [ra];\n\t}"
        :: "r"(local_addr), "r"(rank) : "memory");
}
DINL void mbar_wait(uint32_t a, uint32_t parity) {
    asm volatile(
        "{\n\t.reg .pred P;\n\t"
        "W_%=:\n\t"
        "mbarrier.try_wait.parity.acquire.cta.shared::cta.b64 P, [%0], %1, 0x989680;\n\t"
        "@P bra.uni D_%=;\n\t"
        "bra.uni W_%=;\n\t"
        "D_%=:\n\t}"
        :: "r"(a), "r"(parity) : "memory");
}
DINL void bulk_g2s(uint32_t dst, const void* src, uint32_t bytes, uint32_t mbar) {
    asm volatile(
        "cp.async.bulk.shared::cta.global.mbarrier::complete_tx::bytes [%0], [%1], %2, [%3];"
        :: "r"(dst), "l"(src), "r"(bytes), "r"(mbar) : "memory");
}

DINL uint32_t sw64(uint32_t off) { return off ^ ((off >> 3) & 0x30); }
DINL float tanh_ap(float x) {
    float y;
    asm("tanh.approx.f32 %0, %1;" : "=f"(y) : "f"(x));
    return y;
}
DINL float fast_sigmoid(float x) { return __fmaf_rn(tanh_ap(0.5f * x), 0.5f, 0.5f); }

// ============================================================================
// Fused prep kernel (A + W + bias in one launch; SW64 64B-row layout)
// ============================================================================

constexpr int PK_A = B_SZ * KDIM / 4;
constexpr int PK_W = 4 * HIDN * KDIM / 4;
constexpr int PK_B = 4 * HIDN;
constexpr int PK_TOTAL = PK_A + PK_W + PK_B;

__global__ void pack_all(const float* __restrict__ x, const float* __restrict__ h,
                         const float* __restrict__ Wx0, const float* __restrict__ Wx1,
                         const float* __restrict__ Wx2, const float* __restrict__ Wx3,
                         const float* __restrict__ Wh0, const float* __restrict__ Wh1,
                         const float* __restrict__ Wh2, const float* __restrict__ Wh3,
                         const float* __restrict__ bx0, const float* __restrict__ bx1,
                         const float* __restrict__ bx2, const float* __restrict__ bx3,
                         const float* __restrict__ bh0, const float* __restrict__ bh1,
                         const float* __restrict__ bh2, const float* __restrict__ bh3) {
    int idx = blockIdx.x * blockDim.x + threadIdx.x;
    if (idx < PK_A) {
        int e = idx * 4;
        int m = e >> 10, k = e & 1023;
        const float* src = (k < 512) ? (x + m * 512 + k) : (h + m * 512 + (k - 512));
        float4 v = *reinterpret_cast<const float4*>(src);
        __half2 h0 = __floats2half2_rn(v.x, v.y);
        __half2 h1 = __floats2half2_rn(v.z, v.w);
        uint2 hv;
        hv.x = *reinterpret_cast<uint32_t*>(&h0);
        hv.y = *reinterpret_cast<uint32_t*>(&h1);
        int mt = m >> 7, r = m & 127, kc = k >> 5, cc = k & 31;
        uint32_t off = sw64((uint32_t)(r * 64 + cc * 2));
        *reinterpret_cast<uint2*>(reinterpret_cast<char*>(&g_A[mt][kc][0]) + off) = hv;
    } else if (idx < PK_A + PK_W) {
        int e = (idx - PK_A) * 4;
        int g = e >> 19;
        int rem = e & ((1 << 19) - 1);
        int j = rem >> 10, k = rem & 1023;
        const float* Wx = (g == 0) ? Wx0 : (g == 1) ? Wx1 : (g == 2) ? Wx2 : Wx3;
        const float* Wh = (g == 0) ? Wh0 : (g == 1) ? Wh1 : (g == 2) ? Wh2 : Wh3;
        const float* src = (k < 512) ? (Wx + j * 512 + k) : (Wh + j * 512 + (k - 512));
        float4 v = *reinterpret_cast<const float4*>(src);
        __half2 h0 = __floats2half2_rn(v.x, v.y);
        __half2 h1 = __floats2half2_rn(v.z, v.w);
        uint2 hv;
        hv.x = *reinterpret_cast<uint32_t*>(&h0);
        hv.y = *reinterpret_cast<uint32_t*>(&h1);
        int nblk = j >> 6;
        int row = g * 64 + (j & 63);
        int kc = k >> 5, cc = k & 31;
        uint32_t off = sw64((uint32_t)(row * 64 + cc * 2));
        *reinterpret_cast<uint2*>(reinterpret_cast<char*>(&g_W[nblk][kc][0]) + off) = hv;
    } else if (idx < PK_TOTAL) {
        int t = idx - PK_A - PK_W;
        int g = t >> 9, j = t & 511;
        const float* bx = (g == 0) ? bx0 : (g == 1) ? bx1 : (g == 2) ? bx2 : bx3;
        const float* bh = (g == 0) ? bh0 : (g == 1) ? bh1 : (g == 2) ? bh2 : bh3;
        g_bias[t] = bx[j] + bh[j];
    }
}

// ============================================================================
// tcgen05 cg2 path (compiles only on sm_103a/sm_100a PTX targets)
// ============================================================================
#if TC_OK

// idesc kind::f16 (fp16 in, fp32 accum): M=256 -> bits[24:28]=16, N=256 ->
// bits[17:22]=32, dtype f32 -> bit4. atype/btype f16 = 0.
constexpr uint32_t MMA_IDESC_CG2 = (16u << 24) | ((MMA_N / 8) << 17) | (1u << 4);
// SW64: layout_type=4, version=1 (Blackwell), SBO=32, LBO=1
constexpr uint64_t SMEM_DESC_BASE_SW64 =
    (uint64_t(4) << 61) | (uint64_t(1) << 46) | (uint64_t(32) << 32) | (uint64_t(1) << 16);

DINL uint64_t make_desc(uint32_t smem_addr) {
    return SMEM_DESC_BASE_SW64 | ((uint64_t)(smem_addr >> 4) & 0x3FFF);
}
DINL void mma_f16_ss_cg2(uint32_t d, uint64_t a, uint64_t b, uint32_t idesc, uint32_t en) {
    asm volatile(
        "{\n\t.reg .pred p;\n\t"
        "setp.ne.u32 p, %4, 0;\n\t"
        "tcgen05.mma.cta_group::2.kind::f16 [%0], %1, %2, %3, "
        "{%5, %5, %5, %5, %5, %5, %5, %5}, p;\n\t}"
        :: "r"(d), "l"(a), "l"(b), "r"(idesc), "r"(en), "r"(0u) : "memory");
}
DINL uint32_t cluster_rank() {
    uint32_t r;
    asm("mov.u32 %0, %%cluster_ctarank;" : "=r"(r));
    return r;
}
#define TC_ALLOC2(sm, n)  asm volatile("tcgen05.alloc.cta_group::2.sync.aligned.shared::cta.b32 [%0], %1;" :: "r"(sm), "r"(n) : "memory")
#define TC_DEALLOC2(t, n) asm volatile("tcgen05.dealloc.cta_group::2.sync.aligned.b32 %0, %1;" :: "r"(t), "r"(n))
#define TC_RELINQ2()      asm volatile("tcgen05.relinquish_alloc_permit.cta_group::2.sync.aligned;")
#define TC_COMMIT_MC2(mb, mask) \
    asm volatile("tcgen05.commit.cta_group::2.mbarrier::arrive::one.shared::cluster.multicast::cluster.b64 [%0], %1;" \
                 :: "r"(mb), "h"((uint16_t)(mask)) : "memory")
#define TC_FENCE_AFTER()  asm volatile("tcgen05.fence::after_thread_sync;" ::: "memory")
#define TC_FENCE_BEFORE() asm volatile("tcgen05.fence::before_thread_sync;" ::: "memory")
#define TC_WAIT_LD()      asm volatile("tcgen05.wait::ld.sync.aligned;" ::: "memory")
#define CLUSTER_SYNC()    do { \
    asm volatile("barrier.cluster.arrive.aligned;" ::: "memory"); \
    asm volatile("barrier.cluster.wait.aligned;" ::: "memory"); } while (0)

#define TC_LD_X16(r, addr) \
    asm volatile( \
        "tcgen05.ld.sync.aligned.32x32b.x16.b32 " \
        "{%0, %1, %2, %3, %4, %5, %6, %7, %8, %9, %10, %11, %12, %13, %14, %15}, [%16];" \
        : "=r"((r)[0]), "=r"((r)[1]), "=r"((r)[2]), "=r"((r)[3]), \
          "=r"((r)[4]), "=r"((r)[5]), "=r"((r)[6]), "=r"((r)[7]), \
          "=r"((r)[8]), "=r"((r)[9]), "=r"((r)[10]), "=r"((r)[11]), \
          "=r"((r)[12]), "=r"((r)[13]), "=r"((r)[14]), "=r"((r)[15]) \
        : "r"(addr))
#endif // TC_OK

#if TC_OK
__global__ void __launch_bounds__(TC_THREADS, 2) __cluster_dims__(2, 1, 1)
#else
__global__ void __launch_bounds__(TC_THREADS, 2)
#endif
lstm_tc(const float* __restrict__ c_in, float* __restrict__ out) {
#if TC_OK
    extern __shared__ char smem[];
    const uint32_t sb = smem_u32(smem);
    const int tid  = threadIdx.x;
    const int wid  = tid >> 5;
    const int lane = tid & 31;
    const uint32_t rank = cluster_rank();         // 0 = leader
    const int pair = blockIdx.x >> 1;

    // Work items strided across pairs: item = pair, pair+148, ...
    const int n_items = 3 + (pair < (N_ITEMS - 3 * N_PAIRS));   // 512 = 3*148+68

    const uint32_t full_bar0  = sb + 64;    // 4 bars
    const uint32_t empty_bar0 = sb + 128;   // 4 bars
    const uint32_t done_bar   = sb + 192;
    const uint32_t epi_bar    = sb + 200;

    if (wid == 8) { TC_ALLOC2(sb, 256); TC_RELINQ2(); }
    if (tid == 0) {
        for (int s = 0; s < TCS; s++) {
            // Leader's full bar: own producer (arrive.expect_tx) + peer relay.
            mbar_init(full_bar0 + s * 8, (rank == 0) ? 2u : 1u);
            mbar_init(empty_bar0 + s * 8, 1);
        }
        mbar_init(done_bar, 1);
        mbar_init(epi_bar, 16);               // 8 warps x 2 CTAs (leader only used)
    }
    __syncthreads();
    // All cluster peers' mbarriers must be live before cross-CTA signalling.
    CLUSTER_SYNC();

    uint32_t tmem;
    asm volatile("ld.shared.b32 %0, [%1];" : "=r"(tmem) : "r"(sb));

    if (wid == 8) {
        // ---- Producer (lane 0): stream this CTA's A half + W half ----
        if (lane == 0) {
            for (int t = 0; t < n_items; t++) {
                const int item = pair + t * N_PAIRS;
                const int nblk = item >> 6;
                const int quad = item & 63;
                const char* Abase = reinterpret_cast<const char*>(&g_A[quad * 2 + rank][0][0]);
                const char* Wbase = reinterpret_cast<const char*>(&g_W[nblk][0][0]);
                for (int ch = 0; ch < N_CHUNKS; ch++) {
                    const int g = t * N_CHUNKS + ch;
                    const int s = g & (TCS - 1);
                    if (g >= TCS) mbar_wait(empty_bar0 + s * 8, ((g - TCS) >> 2) & 1);
                    mbar_expect_tx(full_bar0 + s * 8, STAGE_BYTES);
                    uint32_t st = sb + SMEM_HDR + s * STAGE_BYTES;
                    bulk_g2s(st, Abase + ch * A_BYTES, A_BYTES, full_bar0 + s * 8);
                    // W chunk is 16KB (256 rows); this CTA's half is rows
                    // [rank*128, rank*128+128) = contiguous 8KB.
                    bulk_g2s(st + A_BYTES,
                             Wbase + ch * (2 * WH_BYTES) + rank * WH_BYTES,
                             WH_BYTES, full_bar0 + s * 8);
                }
            }
        }
    } else if (wid == 9) {
        if (lane == 0) {
            if (rank == 0) {
                // ---- MMA issuer (leader). full bar counts peer relay too. ----
                for (int t = 0; t < n_items; t++) {
                    if (t > 0) mbar_wait(epi_bar, (t - 1) & 1);
                    for (int ch = 0; ch < N_CHUNKS; ch++) {
                        const int g = t * N_CHUNKS + ch;
                        const int s = g & (TCS - 1);
                        mbar_wait(full_bar0 + s * 8, (g >> 2) & 1);
                        uint32_t st = sb + SMEM_HDR + s * STAGE_BYTES;
                        uint64_t ad = make_desc(st);
                        uint64_t bd = make_desc(st + A_BYTES);
                        const uint32_t en = (ch == 0) ? 0u : 1u;
                        mma_f16_ss_cg2(tmem, ad + 0, bd + 0, MMA_IDESC_CG2, en);
                        mma_f16_ss_cg2(tmem, ad + 2, bd + 2, MMA_IDESC_CG2, 1u);
                        TC_COMMIT_MC2(empty_bar0 + s * 8, 0x3);
                    }
                    TC_COMMIT_MC2(done_bar, 0x3);
                }
            } else {
                // ---- Relay (peer): local full -> arrive on leader's full ----
                const int total = n_items * N_CHUNKS;
                for (int g = 0; g < total; g++) {
                    const int s = g & (TCS - 1);
                    mbar_wait(full_bar0 + s * 8, (g >> 2) & 1);
                    mbar_arrive_cluster(full_bar0 + s * 8, 0);
                }
            }
        }
    } else {
        // ---- 8 epilogue warps per CTA over this CTA's M-half (128 rows).
        // Warp w: subpartition sp=w&3 (rows sp*32+lane), half=(w>>2)&1.
        const int sp = wid & 3, half = (wid >> 2) & 1;
        const int r = sp * 32 + lane;

        for (int t = 0; t < n_items; t++) {
            mbar_wait(done_bar, t & 1);
            TC_FENCE_AFTER();

            const int item = pair + t * N_PAIRS;
            const int nblk = item >> 6;
            const int quad = item & 63;
            const int c0   = nblk * 64;
            const int mrow = quad * 256 + (int)rank * 128 + r;
            const float* crow = c_in + (size_t)mrow * HIDN + c0;
            float*       hrow = out + (size_t)mrow * HIDN + c0;
            float*       orow = out + (size_t)B_SZ * HIDN + (size_t)mrow * HIDN + c0;

            #pragma unroll
            for (int jb = 0; jb < 2; jb++) {
                const int j = half * 32 + jb * 16;
                uint32_t ri[16], rg[16], rf[16], ro[16];
                TC_LD_X16(ri, tmem + 0 + j);
                TC_LD_X16(rg, tmem + 64 + j);
                TC_LD_X16(rf, tmem + 128 + j);
                TC_LD_X16(ro, tmem + 192 + j);
                TC_WAIT_LD();

                float cv[16];
                #pragma unroll
                for (int q = 0; q < 4; q++)
                    *reinterpret_cast<float4*>(&cv[q * 4]) =
                        *reinterpret_cast<const float4*>(crow + j + q * 4);

                const float* bi = g_bias + c0 + j;
                #pragma unroll
                for (int q = 0; q < 16; q++) {
                    float iv = fast_sigmoid(__uint_as_float(ri[q]) + bi[q]);
                    float gv = tanh_ap(__uint_as_float(rg[q]) + bi[512 + q]);
                    float fv = fast_sigmoid(__uint_as_float(rf[q]) + bi[1024 + q]);
                    float ov = fast_sigmoid(__uint_as_float(ro[q]) + bi[1536 + q]);
                    float c2 = fv * cv[q] + iv * gv;
                    rg[q] = __float_as_uint(c2);
                    ri[q] = __float_as_uint(ov * tanh_ap(c2));
                }
                #pragma unroll
                for (int q = 0; q < 4; q++) {
                    *reinterpret_cast<float4*>(hrow + j + q * 4) =
                        *reinterpret_cast<const float4*>(&ri[q * 4]);
                    *reinterpret_cast<float4*>(orow + j + q * 4) =
                        *reinterpret_cast<const float4*>(&rg[q * 4]);
                }
            }
            // Release D for next tile: all 16 warps (both CTAs) on leader's bar.
            TC_FENCE_BEFORE();
            if (lane == 0) mbar_arrive_cluster(epi_bar, 0);
        }
    }

    __syncthreads();
    if (wid == 8) { TC_DEALLOC2(tmem, 256); }
    // No CTA may exit while its pair peer might still signal into its SMEM.
    CLUSTER_SYNC();
#endif // TC_OK
}

// ============================================================================
// Fallback (plain sm_103 cubin only; never selected on the 'a' builds the
// bench has loaded every round): simple SIMT GEMM over the packed tiles.
// ============================================================================

__global__ void lstm_fb(const float* __restrict__ c_in, float* __restrict__ out) {
    int gidx = blockIdx.x * blockDim.x + threadIdx.x;
    if (gidx >= B_SZ * HIDN) return;
    int m = gidx >> 9;
    int jcol = gidx & 511;
    int nblk = jcol >> 6, jj = jcol & 63;
    int mt = m >> 7, r = m & 127;

    float acc[4] = {0.f, 0.f, 0.f, 0.f};
    for (int kc = 0; kc < N_CHUNKS; kc++) {
        const __half* At = &g_A[mt][kc][0];
        const __half* Wt = &g_W[nblk][kc][0];
        for (int cc = 0; cc < K_CHUNK; cc++) {
            float av = __half2float(*reinterpret_cast<const __half*>(
                reinterpret_cast<const char*>(At) + sw64((uint32_t)(r * 64 + cc * 2))));
            #pragma unroll
            for (int g = 0; g < 4; g++) {
                int row = g * 64 + jj;
                float wv = __half2float(*reinterpret_cast<const __half*>(
                    reinterpret_cast<const char*>(Wt) + sw64((uint32_t)(row * 64 + cc * 2))));
                acc[g] += av * wv;
            }
        }
    }
    int c0 = nblk * 64;
    float iv = fast_sigmoid(acc[0] + g_bias[c0 + jj]);
    float gv = tanh_ap     (acc[1] + g_bias[512 + c0 + jj]);
    float fv = fast_sigmoid(acc[2] + g_bias[1024 + c0 + jj]);
    float ov = fast_sigmoid(acc[3] + g_bias[1536 + c0 + jj]);
    float cv = c_in[m * HIDN + jcol];
    float cn = fv * cv + iv * gv;
    out[m * HIDN + jcol] = ov * tanh_ap(cn);
    out[B_SZ * HIDN + m * HIDN + jcol] = cn;
}

// ============================================================================
// Launch
// ============================================================================

extern "C" void kernel_launch(void* const* d_in, const int* in_sizes, int n_in,
                              void* d_out, int out_size) {
    const float* x = (const float*)d_in[0];
    const float* h = (const float*)d_in[1];
    const float* c = (const float*)d_in[2];
    // gate order in packed layout: 0=i, 1=g, 2=f, 3=o
    const float* Wxi = (const float*)d_in[3];  const float* bxi = (const float*)d_in[4];
    const float* Wxo = (const float*)d_in[5];  const float* bxo = (const float*)d_in[6];
    const float* Wxf = (const float*)d_in[7];  const float* bxf = (const float*)d_in[8];
    const float* Wxg = (const float*)d_in[9];  const float* bxg = (const float*)d_in[10];
    const float* Whi = (const float*)d_in[11]; const float* bhi = (const float*)d_in[12];
    const float* Who = (const float*)d_in[13]; const float* bho = (const float*)d_in[14];
    const float* Whf = (const float*)d_in[15]; const float* bhf = (const float*)d_in[16];
    const float* Whg = (const float*)d_in[17]; const float* bhg = (const float*)d_in[18];

    pack_all<<<(PK_TOTAL + 255) / 256, 256>>>(
        x, h, Wxi, Wxg, Wxf, Wxo, Whi, Whg, Whf, Who,
        bxi, bxg, bxf, bxo, bhi, bhg, bhf, bho);

    // Host-side path selection: the tcgen05 kernel only has a real body when
    // the loaded cubin came from a 103a-feature gencode pass.
    cudaFuncAttributes attr;
    cudaFuncGetAttributes(&attr, lstm_tc);
    const bool use_tc = attr.numRegs > 40;

    if (use_tc) {
        cudaFuncSetAttribute(lstm_tc, cudaFuncAttributeMaxDynamicSharedMemorySize, SMEM_TOTAL_TC);
        lstm_tc<<<GRID_X, TC_THREADS, SMEM_TOTAL_TC>>>(c, (float*)d_out);
    } else {
        lstm_fb<<<(B_SZ * HIDN + 255) / 256, 256>>>(c, (float*)d_out);
    }
}